// round 2
// baseline (speedup 1.0000x reference)
#include <cuda_runtime.h>
#include <math.h>

// Problem dims
#define BB 32
#define TT 2048
#define HH 16
#define HD 128
#define CC 2048          // H*HD
#define TCH 256          // attention T-chunk
#define NCH 8            // T / TCH

// ---------------- scratch (device globals; no allocation allowed) ----------------
__device__ float g_h[BB * CC];             // LN1 out
__device__ float g_qkv[BB * 3 * CC];       // qkv
__device__ float g_part[64 * BB * CC];     // split-K partials (max 64 chunks * 32 * 2048)
__device__ float g_ao[BB * CC];            // attention output (B, C)
__device__ float g_x1[BB * CC];            // x + attn_proj
__device__ float g_h2[BB * CC];            // LN2 out
__device__ float g_fc[BB * 4 * CC];        // gelu(fc)
__device__ float g_pm[BB * HH * NCH];      // partial max
__device__ float g_pl[BB * HH * NCH];      // partial sumexp
__device__ float g_po[BB * HH * NCH * HD]; // partial weighted V sums

// Device-side buffer selector so kernel_launch contains ONLY kernel launches
// (no cudaGetSymbolAddress / runtime API inside the captured region).
#define BUF_H   0
#define BUF_QKV 1
#define BUF_AO  3
#define BUF_X1  4
#define BUF_H2  5
#define BUF_FC  6
__device__ __forceinline__ float* dev_buf(int id) {
    switch (id) {
        case BUF_H:   return g_h;
        case BUF_QKV: return g_qkv;
        case BUF_AO:  return g_ao;
        case BUF_X1:  return g_x1;
        case BUF_H2:  return g_h2;
        case BUF_FC:  return g_fc;
    }
    return nullptr;
}

// ---------------- f32x2 packed-FMA helpers (Blackwell sm_100+) ----------------
__device__ __forceinline__ unsigned long long f32x2_pack(float lo, float hi) {
    unsigned long long r;
    asm("mov.b64 %0, {%1, %2};" : "=l"(r) : "f"(lo), "f"(hi));
    return r;
}
__device__ __forceinline__ void f32x2_fma(unsigned long long& d,
                                          unsigned long long a,
                                          unsigned long long b) {
    asm("fma.rn.f32x2 %0, %1, %2, %3;" : "=l"(d) : "l"(a), "l"(b), "l"(d));
}
__device__ __forceinline__ float2 f32x2_unpack(unsigned long long v) {
    float lo, hi;
    asm("mov.b64 {%0, %1}, %2;" : "=f"(lo), "=f"(hi) : "l"(v));
    return make_float2(lo, hi);
}

// ---------------- LayerNorm: one block per row ----------------
// src: external pointer if src_id < 0, else device buffer. dst: device buffer.
__global__ __launch_bounds__(256) void ln_kernel(const float* __restrict__ x_ext,
                                                 int src_id,
                                                 const float* __restrict__ sc,
                                                 const float* __restrict__ bi,
                                                 int dst_id) {
    const float* x = (src_id < 0) ? x_ext : dev_buf(src_id);
    float* y = dev_buf(dst_id);
    const int b = blockIdx.x, tid = threadIdx.x;
    const int warp = tid >> 5, lane = tid & 31;
    const float* xr = x + b * CC;
    float v[8];
    float s = 0.f;
#pragma unroll
    for (int i = 0; i < 8; i++) { v[i] = xr[tid + i * 256]; s += v[i]; }
    __shared__ float red[8];
#pragma unroll
    for (int o = 16; o > 0; o >>= 1) s += __shfl_xor_sync(0xffffffffu, s, o);
    if (lane == 0) red[warp] = s;
    __syncthreads();
    s = red[0];
#pragma unroll
    for (int i = 1; i < 8; i++) s += red[i];
    const float mean = s * (1.f / (float)CC);
    float q = 0.f;
#pragma unroll
    for (int i = 0; i < 8; i++) { float d = v[i] - mean; q += d * d; }
    __syncthreads();
#pragma unroll
    for (int o = 16; o > 0; o >>= 1) q += __shfl_xor_sync(0xffffffffu, q, o);
    if (lane == 0) red[warp] = q;
    __syncthreads();
    q = red[0];
#pragma unroll
    for (int i = 1; i < 8; i++) q += red[i];
    const float r = rsqrtf(q * (1.f / (float)CC) + 1e-5f);
#pragma unroll
    for (int i = 0; i < 8; i++) {
        const int n = tid + i * 256;
        y[b * CC + n] = (v[i] - mean) * r * sc[n] + bi[n];
    }
}

// ---------------- split-K GEMM partial: g_part[chunk][32][N] = A[32,Kchunk] @ W ----------------
// 256 threads; each thread owns 2 output columns (float2), all 32 rows.
// A tile (32x32) staged in SMEM as duplicated f32x2 pairs: inner loop is
// 16x LDS.128 + 32x FFMA2 per k -> FMA-pipe bound at ~2x scalar fp32 rate.
__global__ __launch_bounds__(256) void gemm_partial(int a_id,
                                                    const float* __restrict__ W,
                                                    int K, int N, int kchunk) {
    const float* A = dev_buf(a_id);
    __shared__ unsigned long long sD[32 * 32];
    const int tid = threadIdx.x;
    const int n = blockIdx.x * 512 + tid * 2;
    const int kb0 = blockIdx.y * kchunk;
    unsigned long long acc[32];
#pragma unroll
    for (int m = 0; m < 32; m++) acc[m] = 0ULL;

    const int lm = tid >> 3;         // 0..31  (row)
    const int lk = (tid & 7) << 2;   // 0,4,...,28

    for (int ks = 0; ks < kchunk; ks += 32) {
        const int kb = kb0 + ks;
        const float4 a4 = *(const float4*)&A[lm * K + kb + lk];
        sD[(lk + 0) * 32 + lm] = f32x2_pack(a4.x, a4.x);
        sD[(lk + 1) * 32 + lm] = f32x2_pack(a4.y, a4.y);
        sD[(lk + 2) * 32 + lm] = f32x2_pack(a4.z, a4.z);
        sD[(lk + 3) * 32 + lm] = f32x2_pack(a4.w, a4.w);
        __syncthreads();
#pragma unroll 4
        for (int kk = 0; kk < 32; kk++) {
            const float2 w2 = *(const float2*)&W[(size_t)(kb + kk) * N + n];
            const unsigned long long wp = f32x2_pack(w2.x, w2.y);
            const unsigned long long* row = &sD[kk * 32];
#pragma unroll
            for (int m2 = 0; m2 < 16; m2++) {
                const ulonglong2 p = *(const ulonglong2*)&row[m2 * 2];
                f32x2_fma(acc[m2 * 2 + 0], p.x, wp);
                f32x2_fma(acc[m2 * 2 + 1], p.y, wp);
            }
        }
        __syncthreads();
    }
#pragma unroll
    for (int m = 0; m < 32; m++) {
        *(float2*)&g_part[((size_t)blockIdx.y * 32 + m) * N + n] = f32x2_unpack(acc[m]);
    }
}

// ---------------- split-K reduce + bias (+gelu) (+residual) ----------------
// resid: external if resid_id < 0 (may be null), else device buffer.
// dst: external (d_out) if dst_id < 0, else device buffer.
__global__ __launch_bounds__(256) void reduce_ep(const float* __restrict__ bias,
                                                 const float* __restrict__ resid_ext,
                                                 int resid_id,
                                                 float* __restrict__ dst_ext,
                                                 int dst_id,
                                                 int N, int nchunk, int do_gelu) {
    const float* resid = (resid_id < 0) ? resid_ext : dev_buf(resid_id);
    float* dst = (dst_id < 0) ? dst_ext : dev_buf(dst_id);
    const int i = blockIdx.x * 256 + threadIdx.x;
    const int total = 32 * N;
    if (i >= total) return;
    const int n = i % N;
    float s = 0.f;
    for (int c = 0; c < nchunk; c++) s += g_part[(size_t)c * total + i];
    s += bias[n];
    if (do_gelu) {
        const float x3 = s * s * s;
        s = 0.5f * s * (1.f + tanhf(0.7978845608028654f * (s + 0.044715f * x3)));
    }
    if (resid) s += resid[i];
    dst[i] = s;
}

// ---------------- copy k_new / v_new outputs from qkv ----------------
__global__ void copy_kv(float* __restrict__ ok, float* __restrict__ ov) {
    const int i = blockIdx.x * 256 + threadIdx.x;
    if (i >= BB * CC) return;
    const int b = i >> 11, c = i & (CC - 1);
    ok[i] = g_qkv[b * 3 * CC + CC + c];
    ov[i] = g_qkv[b * 3 * CC + 2 * CC + c];
}

// ---------------- flash-decode attention partial over one T chunk ----------------
__global__ __launch_bounds__(128) void attn_partial(const float* __restrict__ Kc,
                                                    const float* __restrict__ Vc,
                                                    const int* __restrict__ pos) {
    const int c = blockIdx.x, h = blockIdx.y, b = blockIdx.z;
    const int p = pos[b];
    const int tbase = c * TCH;
    if (tbase > p) return;
    const int tcnt = min(TCH, p + 1 - tbase);
    __shared__ float s[TCH];
    __shared__ float red[4];
    const int tid = threadIdx.x, warp = tid >> 5, lane = tid & 31;

    // Phase 1: scores. Each warp handles one t at a time (LDG.128 per lane).
    const float4 qv = *(const float4*)&g_qkv[b * 3 * CC + h * HD + lane * 4];
    for (int t = warp; t < tcnt; t += 4) {
        const float4 kv =
            *(const float4*)&Kc[((size_t)(b * TT + tbase + t) * HH + h) * HD + lane * 4];
        float d = qv.x * kv.x + qv.y * kv.y + qv.z * kv.z + qv.w * kv.w;
#pragma unroll
        for (int o = 16; o > 0; o >>= 1) d += __shfl_xor_sync(0xffffffffu, d, o);
        if (lane == 0) s[t] = d * 0.08838834764831845f;  // 1/sqrt(128)
    }
    __syncthreads();

    // Phase 2: block max
    float mx = -3.4e38f;
    for (int t = tid; t < tcnt; t += 128) mx = fmaxf(mx, s[t]);
#pragma unroll
    for (int o = 16; o > 0; o >>= 1) mx = fmaxf(mx, __shfl_xor_sync(0xffffffffu, mx, o));
    if (lane == 0) red[warp] = mx;
    __syncthreads();
    mx = fmaxf(fmaxf(red[0], red[1]), fmaxf(red[2], red[3]));

    // exp + sum (each thread touches only its own t's)
    float sum = 0.f;
    for (int t = tid; t < tcnt; t += 128) {
        const float e = __expf(s[t] - mx);
        s[t] = e;
        sum += e;
    }
    __syncthreads();  // protect red reuse AND publish s[] exp values
#pragma unroll
    for (int o = 16; o > 0; o >>= 1) sum += __shfl_xor_sync(0xffffffffu, sum, o);
    if (lane == 0) red[warp] = sum;
    __syncthreads();
    sum = red[0] + red[1] + red[2] + red[3];

    // Phase 3: weighted V accumulation; thread = head-dim element
    float acc = 0.f;
    const float* vp = &Vc[((size_t)(b * TT + tbase) * HH + h) * HD + tid];
    int t = 0;
    for (; t + 4 <= tcnt; t += 4) {
        const float v0 = vp[(size_t)(t + 0) * CC];
        const float v1 = vp[(size_t)(t + 1) * CC];
        const float v2 = vp[(size_t)(t + 2) * CC];
        const float v3 = vp[(size_t)(t + 3) * CC];
        acc += s[t] * v0 + s[t + 1] * v1 + s[t + 2] * v2 + s[t + 3] * v3;
    }
    for (; t < tcnt; t++) acc += s[t] * vp[(size_t)t * CC];

    const int idx = (b * HH + h) * NCH + c;
    g_po[idx * HD + tid] = acc;
    if (tid == 0) { g_pm[idx] = mx; g_pl[idx] = sum; }
}

// ---------------- combine flash-decode partials -> g_ao ----------------
__global__ __launch_bounds__(128) void attn_combine(const int* __restrict__ pos) {
    const int bh = blockIdx.x;
    const int b = bh >> 4, h = bh & 15;
    const int nch = (pos[b] >> 8) + 1;  // valid chunks
    const int tid = threadIdx.x;
    float gm = -3.4e38f;
    for (int c = 0; c < nch; c++) gm = fmaxf(gm, g_pm[bh * NCH + c]);
    float l = 0.f, acc = 0.f;
    for (int c = 0; c < nch; c++) {
        const float w = __expf(g_pm[bh * NCH + c] - gm);
        l += g_pl[bh * NCH + c] * w;
        acc += g_po[(bh * NCH + c) * HD + tid] * w;
    }
    g_ao[b * CC + h * HD + tid] = acc / l;
}

// ---------------- launch: kernel launches ONLY ----------------
extern "C" void kernel_launch(void* const* d_in, const int* in_sizes, int n_in,
                              void* d_out, int out_size) {
    const float* x           = (const float*)d_in[0];
    const float* prev_k      = (const float*)d_in[1];
    const float* prev_v      = (const float*)d_in[2];
    const int*   pos         = (const int*)d_in[3];
    const float* ln1_scale   = (const float*)d_in[4];
    const float* ln1_bias    = (const float*)d_in[5];
    const float* w_attn      = (const float*)d_in[6];
    const float* b_attn      = (const float*)d_in[7];
    const float* w_attn_proj = (const float*)d_in[8];
    const float* b_attn_proj = (const float*)d_in[9];
    const float* ln2_scale   = (const float*)d_in[10];
    const float* ln2_bias    = (const float*)d_in[11];
    const float* w_fc        = (const float*)d_in[12];
    const float* b_fc        = (const float*)d_in[13];
    const float* w_mlp_proj  = (const float*)d_in[14];
    const float* b_mlp_proj  = (const float*)d_in[15];
    float* out = (float*)d_out;   // [x (65536) | k_new (65536) | v_new (65536)]

    // 1. LN1: x -> g_h
    ln_kernel<<<32, 256>>>(x, -1, ln1_scale, ln1_bias, BUF_H);
    // 2. qkv = g_h @ w_attn + b  (K=2048, N=6144; 16 K-chunks of 128)
    gemm_partial<<<dim3(12, 16), 256>>>(BUF_H, w_attn, 2048, 6144, 128);
    reduce_ep<<<(32 * 6144 + 255) / 256, 256>>>(b_attn, nullptr, -1, nullptr, BUF_QKV,
                                                6144, 16, 0);
    // 3. emit k_new / v_new outputs
    copy_kv<<<(BB * CC + 255) / 256, 256>>>(out + 65536, out + 131072);
    // 4. flash-decode attention -> g_ao
    attn_partial<<<dim3(NCH, HH, BB), 128>>>(prev_k, prev_v, pos);
    attn_combine<<<BB * HH, 128>>>(pos);
    // 5. attn_proj + residual(x): g_ao @ w_attn_proj + b + x -> g_x1
    //    (K=2048, N=2048; 32 K-chunks of 64)
    gemm_partial<<<dim3(4, 32), 256>>>(BUF_AO, w_attn_proj, 2048, 2048, 64);
    reduce_ep<<<(32 * 2048 + 255) / 256, 256>>>(b_attn_proj, x, -1, nullptr, BUF_X1,
                                                2048, 32, 0);
    // 6. LN2: g_x1 -> g_h2
    ln_kernel<<<32, 256>>>(nullptr, BUF_X1, ln2_scale, ln2_bias, BUF_H2);
    // 7. fc + gelu: g_h2 @ w_fc -> gelu -> g_fc  (K=2048, N=8192; 16 K-chunks of 128)
    gemm_partial<<<dim3(16, 16), 256>>>(BUF_H2, w_fc, 2048, 8192, 128);
    reduce_ep<<<(32 * 8192 + 255) / 256, 256>>>(b_fc, nullptr, -1, nullptr, BUF_FC,
                                                8192, 16, 1);
    // 8. mlp_proj + residual(g_x1) -> out x  (K=8192, N=2048; 64 K-chunks of 128)
    gemm_partial<<<dim3(4, 64), 256>>>(BUF_FC, w_mlp_proj, 8192, 2048, 128);
    reduce_ep<<<(32 * 2048 + 255) / 256, 256>>>(b_mlp_proj, nullptr, BUF_X1, out, -1,
                                                2048, 64, 0);
}